// round 8
// baseline (speedup 1.0000x reference)
#include <cuda_runtime.h>
#include <cstdint>
#include <cstddef>

// Problem dims
#define TT 1024
#define BB 64
#define HH 256
#define WPADI 260   // wih SMEM row stride (floats)
#define NTHR 512

// Fused persistent kernel. 128 CTAs = 2 dirs x 8 grps x 8 slices, 512 thr.
// CTA: 32 hidden (96 gate rows) x 8 batches, K=256 for both GEMMs.
// Thread (jg 0..31, ks 0..15): 3 gate rows x 16-k slice.
//   W_hh slice: registers (48 floats = 24 f32x2)  -> ~120 regs total, 4 w/SMSP.
//   W_ih slice: SMEM; x[t]: SMEM double buffer (reg prefetch 1 step ahead).
// gx GEMM runs BEFORE the peer-flag poll (R6-proven ordering: skew hides
// under gx). 4-stage butterfly reduce over ks; lane pair (2m,2m+1) both end
// with full gate sums for batch m; even lane stores.

__device__ float    g_h[2][2][8][8][256];   // [dir][buf][grp][b][k]
__device__ unsigned g_flag[2][8][8];        // per (dir,grp,slice) step flag
__device__ unsigned g_cnt[16 * 32];         // init barrier (128B-strided)
__device__ unsigned g_phs[16 * 32];

// ---------------------------------------------------------------------------
// Helpers
// ---------------------------------------------------------------------------
__device__ __forceinline__ unsigned long long ffma2(
    unsigned long long a, unsigned long long b, unsigned long long c) {
    unsigned long long d;
    asm("fma.rn.f32x2 %0, %1, %2, %3;" : "=l"(d) : "l"(a), "l"(b), "l"(c));
    return d;
}
__device__ __forceinline__ float pair_sum(unsigned long long p) {
    float lo, hi;
    asm("mov.b64 {%0, %1}, %2;" : "=f"(lo), "=f"(hi) : "l"(p));
    return lo + hi;
}
__device__ __forceinline__ float fast_sigmoid(float x) {
    return 1.0f / (1.0f + __expf(-x));
}
__device__ __forceinline__ float fast_tanh(float x) {
    return 2.0f / (1.0f + __expf(-2.0f * x)) - 1.0f;
}
// float4-chunk swizzle within a 256-float row (64 chunks of 16B).
__device__ __forceinline__ int swz(int q) {
    return (q & ~7) | ((q ^ (q >> 3)) & 7);
}

// One-time replay-safe group barrier (phase monotonic across replays).
__device__ __forceinline__ void grp_barrier_init(int gi) {
    __syncthreads();
    if (threadIdx.x == 0) {
        unsigned* cnt = &g_cnt[gi * 32];
        unsigned* phs = &g_phs[gi * 32];
        unsigned ph;
        asm volatile("ld.acquire.gpu.global.u32 %0, [%1];"
                     : "=r"(ph) : "l"(phs) : "memory");
        unsigned prev;
        asm volatile("atom.acq_rel.gpu.global.add.u32 %0, [%1], %2;"
                     : "=r"(prev) : "l"(cnt), "r"(1u) : "memory");
        if (prev == 7u) {
            asm volatile("st.relaxed.gpu.global.u32 [%0], %1;"
                         :: "l"(cnt), "r"(0u) : "memory");
            asm volatile("red.release.gpu.global.add.u32 [%0], %1;"
                         :: "l"(phs), "r"(1u) : "memory");
        } else {
            unsigned cur;
            do {
                asm volatile("ld.acquire.gpu.global.u32 %0, [%1];"
                             : "=r"(cur) : "l"(phs) : "memory");
            } while (cur == ph);
        }
    }
    __syncthreads();
}

// ---------------------------------------------------------------------------
// Fused persistent LSTM kernel. grid=128, block=512.
// SMEM: wih_s[96][WPADI] + hs[2][2048] + xs[2][2048]  (~130 KB)
// ---------------------------------------------------------------------------
__global__ void __launch_bounds__(NTHR, 1) lstm_fused(
    const float* __restrict__ X,
    const float* __restrict__ wih_f, const float* __restrict__ whh_f,
    const float* __restrict__ bih_f, const float* __restrict__ bhh_f,
    const float* __restrict__ wih_b, const float* __restrict__ whh_b,
    const float* __restrict__ bih_b, const float* __restrict__ bhh_b,
    float* __restrict__ out)
{
    extern __shared__ float sm[];
    float* wih_s = sm;                       // 96 * WPADI
    float* hs    = sm + 96 * WPADI;          // 2 * 2048
    float* xs    = hs + 2 * 2048;            // 2 * 2048

    const int bx  = blockIdx.x;
    const int dir = bx >> 6;
    const int grp = (bx >> 3) & 7;
    const int sl  = bx & 7;
    const int j0  = sl * 32;
    const int gi  = dir * 8 + grp;

    const float* whh = dir ? whh_b : whh_f;
    const float* wih = dir ? wih_b : wih_f;
    const float* bih = dir ? bih_b : bih_f;
    const float* bhh = dir ? bhh_b : bhh_f;

    const int tid  = threadIdx.x;
    const int lane = tid & 31;
    const int warp = tid >> 5;
    const int jg   = warp * 2 + (lane >> 4);   // hidden within slice 0..31
    const int ks   = lane & 15;                // k-slice 0..15 (16 floats each)
    const int j    = j0 + jg;
    const int col  = ks * 16;
    const int bOwn = ks >> 1;                  // owned batch after reduce
    const int bG   = grp * 8 + bOwn;
    const bool ev  = (ks & 1) == 0;            // storing lane of the pair

    // Per-thread staging index (1 float4 for h and x buffers).
    const int fb = tid >> 6, fq = tid & 63;
    const int dsw = fb * 256 + swz(fq) * 4;

    // --- W_hh slice into REGISTERS: 3 rows x 16 k = 24 f32x2. ---
    unsigned long long w0r[8], w1r[8], w2r[8];
#pragma unroll
    for (int g = 0; g < 3; g++) {
        const float* base = whh + (size_t)(g * 256 + j) * 256 + col;
        unsigned long long* dst = (g == 0) ? w0r : (g == 1) ? w1r : w2r;
#pragma unroll
        for (int c = 0; c < 4; c++) {
            ulonglong2 wv = *(const ulonglong2*)(base + c * 4);
            dst[2 * c]     = wv.x;
            dst[2 * c + 1] = wv.y;
        }
    }

    // --- W_ih slice into SMEM (swizzled 16B chunks). 96*64 chunks. ---
    for (int idx = tid; idx < 96 * 64; idx += NTHR) {
        int r = idx >> 6, q = idx & 63;
        int grow = (r >> 5) * 256 + j0 + (r & 31);
        float4 v = *(const float4*)(wih + (size_t)grow * 256 + q * 4);
        *(float4*)(wih_s + r * WPADI + swz(q) * 4) = v;
    }

    const float bias0 = bih[j]       + bhh[j];
    const float bias1 = bih[256 + j] + bhh[256 + j];
    const float bias2 = bih[512 + j] + bhh[512 + j];

    // Zero h buffer 0; stage x for t0 into xs buffer 0 (1 float4/thread).
    *(float4*)(hs + tid * 4) = make_float4(0.f, 0.f, 0.f, 0.f);
    {
        const int t0 = dir ? (TT - 1) : 0;
        float4 v = __ldcg((const float4*)(
            X + ((size_t)(grp * 8 + fb) * TT + t0) * 256 + fq * 4));
        *(float4*)(xs + dsw) = v;
    }
    if (tid == 0)
        asm volatile("st.relaxed.gpu.global.u32 [%0], %1;"
                     :: "l"(&g_flag[dir][grp][sl]), "r"(0u) : "memory");
    grp_barrier_init(gi);

    float c_reg = 0.0f;

    for (int s = 0; s < TT; s++) {
        const int t = dir ? (TT - 1 - s) : s;

        // --- Prefetch x[t(s+1)] into registers (1 float4). ---
        float4 xp;
        if (s + 1 < TT) {
            const int tn = dir ? (t - 1) : (t + 1);
            xp = __ldcg((const float4*)(
                X + ((size_t)(grp * 8 + fb) * TT + tn) * 256 + fq * 4));
        }

        // --- gx GEMM: W_ih (SMEM) x x[t] (SMEM); independent of peers. ---
        unsigned long long P0[8], P1[8], P2[8];
#pragma unroll
        for (int b = 0; b < 8; b++) { P0[b] = 0ull; P1[b] = 0ull; P2[b] = 0ull; }

        const float* xb = xs + (s & 1) * 2048;
#pragma unroll
        for (int c = 0; c < 4; c++) {
            const int off = swz(ks * 4 + c) * 4;
            ulonglong2 w0 = *(const ulonglong2*)(wih_s + (jg)      * WPADI + off);
            ulonglong2 w1 = *(const ulonglong2*)(wih_s + (32 + jg) * WPADI + off);
            ulonglong2 w2 = *(const ulonglong2*)(wih_s + (64 + jg) * WPADI + off);
#pragma unroll
            for (int b = 0; b < 8; b++) {
                ulonglong2 hv = *(const ulonglong2*)(xb + b * 256 + off);
                P0[b] = ffma2(w0.x, hv.x, P0[b]);
                P1[b] = ffma2(w1.x, hv.x, P1[b]);
                P2[b] = ffma2(w2.x, hv.x, P2[b]);
                P0[b] = ffma2(w0.y, hv.y, P0[b]);
                P1[b] = ffma2(w1.y, hv.y, P1[b]);
                P2[b] = ffma2(w2.y, hv.y, P2[b]);
            }
        }

        // --- Poll peers (released ~when we started this step), stage h. ---
        float* hb = hs + (s & 1) * 2048;
        if (s > 0) {
            if (tid < 8) {
                const unsigned* f = &g_flag[dir][grp][tid];
                unsigned v;
                do {
                    asm volatile("ld.acquire.gpu.global.u32 %0, [%1];"
                                 : "=r"(v) : "l"(f) : "memory");
                } while (v < (unsigned)s);
            }
            __syncthreads();
            float4 v = __ldcg(
                (const float4*)&g_h[dir][s & 1][grp][0][0] + tid);
            *(float4*)(hb + dsw) = v;
            __syncthreads();
        }

        // --- Recurrent GEMM: W_hh (regs) x h (SMEM), same accumulators. ---
#pragma unroll
        for (int c = 0; c < 4; c++) {
            const int off = swz(ks * 4 + c) * 4;
#pragma unroll
            for (int b = 0; b < 8; b++) {
                ulonglong2 hv = *(const ulonglong2*)(hb + b * 256 + off);
                P0[b] = ffma2(w0r[2 * c],     hv.x, P0[b]);
                P1[b] = ffma2(w1r[2 * c],     hv.x, P1[b]);
                P2[b] = ffma2(w2r[2 * c],     hv.x, P2[b]);
                P0[b] = ffma2(w0r[2 * c + 1], hv.y, P0[b]);
                P1[b] = ffma2(w1r[2 * c + 1], hv.y, P1[b]);
                P2[b] = ffma2(w2r[2 * c + 1], hv.y, P2[b]);
            }
        }

        float a0[8], a1[8], a2[8];
#pragma unroll
        for (int b = 0; b < 8; b++) {
            a0[b] = pair_sum(P0[b]);
            a1[b] = pair_sum(P1[b]);
            a2[b] = pair_sum(P2[b]);
        }

        // --- 4-stage butterfly reduce-scatter over ks (16 lanes). ---
        // Stage xor8: keep batch bit2 = (ks>>3)&1.
        const bool h8 = (ks & 8) != 0;
        float t0a[4], t1a[4], t2a[4];
#pragma unroll
        for (int i = 0; i < 4; i++) {
            float s0 = h8 ? a0[i] : a0[i + 4];
            float s1 = h8 ? a1[i] : a1[i + 4];
            float s2 = h8 ? a2[i] : a2[i + 4];
            t0a[i] = (h8 ? a0[i + 4] : a0[i]) + __shfl_xor_sync(0xffffffffu, s0, 8);
            t1a[i] = (h8 ? a1[i + 4] : a1[i]) + __shfl_xor_sync(0xffffffffu, s1, 8);
            t2a[i] = (h8 ? a2[i + 4] : a2[i]) + __shfl_xor_sync(0xffffffffu, s2, 8);
        }
        // Stage xor4: keep batch bit1 = (ks>>2)&1.
        const bool h4 = (ks & 4) != 0;
        float u0[2], u1[2], u2[2];
#pragma unroll
        for (int i = 0; i < 2; i++) {
            float s0 = h4 ? t0a[i] : t0a[i + 2];
            float s1 = h4 ? t1a[i] : t1a[i + 2];
            float s2 = h4 ? t2a[i] : t2a[i + 2];
            u0[i] = (h4 ? t0a[i + 2] : t0a[i]) + __shfl_xor_sync(0xffffffffu, s0, 4);
            u1[i] = (h4 ? t1a[i + 2] : t1a[i]) + __shfl_xor_sync(0xffffffffu, s1, 4);
            u2[i] = (h4 ? t2a[i + 2] : t2a[i]) + __shfl_xor_sync(0xffffffffu, s2, 4);
        }
        // Stage xor2: keep batch bit0 = (ks>>1)&1.
        const bool h2 = (ks & 2) != 0;
        float v0, v1, v2;
        {
            float s0 = h2 ? u0[0] : u0[1];
            float s1 = h2 ? u1[0] : u1[1];
            float s2 = h2 ? u2[0] : u2[1];
            v0 = (h2 ? u0[1] : u0[0]) + __shfl_xor_sync(0xffffffffu, s0, 2);
            v1 = (h2 ? u1[1] : u1[0]) + __shfl_xor_sync(0xffffffffu, s1, 2);
            v2 = (h2 ? u2[1] : u2[0]) + __shfl_xor_sync(0xffffffffu, s2, 2);
        }
        // Stage xor1: full reduce; both lanes of the pair get batch bOwn.
        float f0 = v0 + __shfl_xor_sync(0xffffffffu, v0, 1);
        float f1 = v1 + __shfl_xor_sync(0xffffffffu, v1, 1);
        float f2 = v2 + __shfl_xor_sync(0xffffffffu, v2, 1);

        f0 += bias0; f1 += bias1; f2 += bias2;

        // --- Coupled-gate pointwise for (hidden j, batch bG); both lanes
        //     of the pair compute identical state; even lane stores. ---
        float ig = fast_sigmoid(f0);
        float cg = fast_tanh(f1);
        float og = fast_sigmoid(f2);
        c_reg = (1.0f - ig) * c_reg + ig * cg;
        float h = og * fast_tanh(c_reg);

        if (s == TT - 1) {
            if (ev) {
                out[(size_t)t * (BB * 2 * HH) + (size_t)bG * (2 * HH)
                    + dir * HH + j] = h;
                size_t base = (size_t)TT * BB * 2 * HH;
                out[base + (size_t)bG * (2 * HH) + dir * HH + j] = h;
                out[base + (size_t)BB * 2 * HH + (size_t)bG * (2 * HH)
                    + dir * HH + j] = c_reg;
            }
        } else {
            if (ev)
                g_h[dir][(s + 1) & 1][grp][bOwn][j] = h;
            // Store prefetched x into next buffer (before the sync that
            // orders it against next step's reads).
            float* xn = xs + ((s + 1) & 1) * 2048;
            *(float4*)(xn + dsw) = xp;
            __syncthreads();   // g_h stores done CTA-wide; xs visible
            if (tid == 0)
                asm volatile("st.release.gpu.global.u32 [%0], %1;"
                             :: "l"(&g_flag[dir][grp][sl]),
                                "r"((unsigned)(s + 1)) : "memory");
            if (ev)
                out[(size_t)t * (BB * 2 * HH) + (size_t)bG * (2 * HH)
                    + dir * HH + j] = h;
        }
    }
}

// ---------------------------------------------------------------------------
// Launch. Inputs: X, wih_f, whh_f, bih_f, bhh_f, wih_b, whh_b, bih_b, bhh_b.
// Output fp32: out[T,B,2H] ++ hn[1,B,2H] ++ cn[1,B,2H].
// ---------------------------------------------------------------------------
extern "C" void kernel_launch(void* const* d_in, const int* in_sizes, int n_in,
                              void* d_out, int out_size) {
    const float* X     = (const float*)d_in[0];
    const float* wih_f = (const float*)d_in[1];
    const float* whh_f = (const float*)d_in[2];
    const float* bih_f = (const float*)d_in[3];
    const float* bhh_f = (const float*)d_in[4];
    const float* wih_b = (const float*)d_in[5];
    const float* whh_b = (const float*)d_in[6];
    const float* bih_b = (const float*)d_in[7];
    const float* bhh_b = (const float*)d_in[8];
    float* out = (float*)d_out;

    const int smem = (96 * WPADI + 2 * 2048 + 2 * 2048) * (int)sizeof(float);
    cudaFuncSetAttribute(lstm_fused, cudaFuncAttributeMaxDynamicSharedMemorySize,
                         smem);

    lstm_fused<<<128, NTHR, smem>>>(X, wih_f, whh_f, bih_f, bhh_f,
                                    wih_b, whh_b, bih_b, bhh_b, out);
}

// round 9
// speedup vs baseline: 1.3017x; 1.3017x over previous
#include <cuda_runtime.h>
#include <cstdint>
#include <cstddef>

// Problem dims
#define TT 1024
#define BB 64
#define HH 256
#define WPADI 260   // wih SMEM row stride (floats)

// Fused persistent kernel (R6 structure, latency-tuned).
// 128 CTAs = 2 dirs x 8 grps x 8 slices, 256 threads.
// Thread (jg 0..31, ks 0..7): 3 gate rows x 32-k slice.
//   W_hh: registers (48 f32x2). W_ih: SMEM. x: SMEM double buffer via cp.async.
// Step: cp.async x(s+1) -> gx half1 -> poll + cp.async h -> gx half2 ->
//       wait0+sync -> rec GEMM (c-outer) -> reduce -> pointwise -> publish.

__device__ float    g_h[2][2][8][8][256];   // [dir][buf][grp][b][k]
__device__ unsigned g_flag[2][8][8];        // per (dir,grp,slice) step flag
__device__ unsigned g_cnt[16 * 32];         // init barrier (128B-strided)
__device__ unsigned g_phs[16 * 32];

// ---------------------------------------------------------------------------
// Helpers
// ---------------------------------------------------------------------------
__device__ __forceinline__ unsigned long long ffma2(
    unsigned long long a, unsigned long long b, unsigned long long c) {
    unsigned long long d;
    asm("fma.rn.f32x2 %0, %1, %2, %3;" : "=l"(d) : "l"(a), "l"(b), "l"(c));
    return d;
}
__device__ __forceinline__ float pair_sum(unsigned long long p) {
    float lo, hi;
    asm("mov.b64 {%0, %1}, %2;" : "=f"(lo), "=f"(hi) : "l"(p));
    return lo + hi;
}
__device__ __forceinline__ float fast_sigmoid(float x) {
    return 1.0f / (1.0f + __expf(-x));
}
__device__ __forceinline__ float fast_tanh(float x) {
    return 2.0f / (1.0f + __expf(-2.0f * x)) - 1.0f;
}
__device__ __forceinline__ uint32_t smem_u32(const void* p) {
    uint32_t a;
    asm("{ .reg .u64 t; cvta.to.shared.u64 t, %1; cvt.u32.u64 %0, t; }"
        : "=r"(a) : "l"(p));
    return a;
}
__device__ __forceinline__ void cp_async16(uint32_t dst, const void* src) {
    asm volatile("cp.async.cg.shared.global [%0], [%1], 16;"
                 :: "r"(dst), "l"(src) : "memory");
}
#define CP_COMMIT() asm volatile("cp.async.commit_group;" ::: "memory")
#define CP_WAIT0()  asm volatile("cp.async.wait_group 0;" ::: "memory")
__device__ __forceinline__ void st_stream(float* p, float v) {
    asm volatile("st.global.cs.f32 [%0], %1;" :: "l"(p), "f"(v) : "memory");
}
// float4-chunk swizzle within a 256-float row (64 chunks of 16B).
__device__ __forceinline__ int swz(int q) {
    return (q & ~7) | ((q ^ (q >> 3)) & 7);
}

// One-time replay-safe group barrier (phase monotonic across replays).
__device__ __forceinline__ void grp_barrier_init(int gi) {
    __syncthreads();
    if (threadIdx.x == 0) {
        unsigned* cnt = &g_cnt[gi * 32];
        unsigned* phs = &g_phs[gi * 32];
        unsigned ph;
        asm volatile("ld.acquire.gpu.global.u32 %0, [%1];"
                     : "=r"(ph) : "l"(phs) : "memory");
        unsigned prev;
        asm volatile("atom.acq_rel.gpu.global.add.u32 %0, [%1], %2;"
                     : "=r"(prev) : "l"(cnt), "r"(1u) : "memory");
        if (prev == 7u) {
            asm volatile("st.relaxed.gpu.global.u32 [%0], %1;"
                         :: "l"(cnt), "r"(0u) : "memory");
            asm volatile("red.release.gpu.global.add.u32 [%0], %1;"
                         :: "l"(phs), "r"(1u) : "memory");
        } else {
            unsigned cur;
            do {
                asm volatile("ld.acquire.gpu.global.u32 %0, [%1];"
                             : "=r"(cur) : "l"(phs) : "memory");
            } while (cur == ph);
        }
    }
    __syncthreads();
}

// ---------------------------------------------------------------------------
// Fused persistent LSTM kernel. grid=128, block=256.
// ---------------------------------------------------------------------------
__global__ void __launch_bounds__(256, 1) lstm_fused(
    const float* __restrict__ X,
    const float* __restrict__ wih_f, const float* __restrict__ whh_f,
    const float* __restrict__ bih_f, const float* __restrict__ bhh_f,
    const float* __restrict__ wih_b, const float* __restrict__ whh_b,
    const float* __restrict__ bih_b, const float* __restrict__ bhh_b,
    float* __restrict__ out)
{
    extern __shared__ float sm[];
    float* wih_s = sm;                       // 96 * WPADI
    float* hs    = sm + 96 * WPADI;          // 2 * 2048
    float* xs    = hs + 2 * 2048;            // 2 * 2048

    const int bx  = blockIdx.x;
    const int dir = bx >> 6;
    const int grp = (bx >> 3) & 7;
    const int sl  = bx & 7;
    const int j0  = sl * 32;
    const int gi  = dir * 8 + grp;

    const float* whh = dir ? whh_b : whh_f;
    const float* wih = dir ? wih_b : wih_f;
    const float* bih = dir ? bih_b : bih_f;
    const float* bhh = dir ? bhh_b : bhh_f;

    const int tid  = threadIdx.x;
    const int lane = tid & 31;
    const int warp = tid >> 5;
    const int jg   = warp * 4 + (lane >> 3);   // hidden within slice 0..31
    const int ks   = lane & 7;                 // k-slice 0..7
    const int j    = j0 + jg;
    const int bG   = grp * 8 + ks;             // this thread's output batch
    const int col  = ks * 32;                  // k-slice base column

    // Per-thread staging indices (2 float4 for h and x buffers).
    const int f0b = tid >> 6,          f0q = tid & 63;
    const int f1b = (tid + 256) >> 6,  f1q = (tid + 256) & 63;
    const int d0  = f0b * 256 + swz(f0q) * 4;   // float index in buffer
    const int d1  = f1b * 256 + swz(f1q) * 4;
    const uint32_t hs_u = smem_u32(hs);
    const uint32_t xs_u = smem_u32(xs);

    // --- W_hh slice into REGISTERS: 3 rows x 32 k = 48 f32x2. ---
    unsigned long long w0r[16], w1r[16], w2r[16];
#pragma unroll
    for (int g = 0; g < 3; g++) {
        const float* base = whh + (size_t)(g * 256 + j) * 256 + col;
        unsigned long long* dst = (g == 0) ? w0r : (g == 1) ? w1r : w2r;
#pragma unroll
        for (int c = 0; c < 8; c++) {
            ulonglong2 wv = *(const ulonglong2*)(base + c * 4);
            dst[2 * c]     = wv.x;
            dst[2 * c + 1] = wv.y;
        }
    }

    // --- W_ih slice into SMEM (swizzled 16B chunks). ---
    for (int idx = tid; idx < 96 * 64; idx += 256) {
        int r = idx >> 6, q = idx & 63;
        int grow = (r >> 5) * 256 + j0 + (r & 31);
        float4 v = *(const float4*)(wih + (size_t)grow * 256 + q * 4);
        *(float4*)(wih_s + r * WPADI + swz(q) * 4) = v;
    }

    const float bias0 = bih[j]       + bhh[j];
    const float bias1 = bih[256 + j] + bhh[256 + j];
    const float bias2 = bih[512 + j] + bhh[512 + j];

    // Zero h buffer 0; stage x for t0 into xs buffer 0.
    for (int idx = tid; idx < 8 * 256; idx += 256) hs[idx] = 0.0f;
    {
        const int t0 = dir ? (TT - 1) : 0;
        float4 v0 = __ldcg((const float4*)(
            X + ((size_t)(grp * 8 + f0b) * TT + t0) * 256 + f0q * 4));
        float4 v1 = __ldcg((const float4*)(
            X + ((size_t)(grp * 8 + f1b) * TT + t0) * 256 + f1q * 4));
        *(float4*)(xs + d0) = v0;
        *(float4*)(xs + d1) = v1;
    }
    if (tid == 0)
        asm volatile("st.relaxed.gpu.global.u32 [%0], %1;"
                     :: "l"(&g_flag[dir][grp][sl]), "r"(0u) : "memory");
    grp_barrier_init(gi);

    float c_reg = 0.0f;

    for (int s = 0; s < TT; s++) {
        const int t = dir ? (TT - 1 - s) : s;

        // --- Kick x(s+1) prefetch via cp.async (no held registers). ---
        if (s + 1 < TT) {
            const int tn = dir ? (t - 1) : (t + 1);
            const uint32_t xd = xs_u + (((s + 1) & 1) * 2048) * 4;
            cp_async16(xd + d0 * 4,
                X + ((size_t)(grp * 8 + f0b) * TT + tn) * 256 + f0q * 4);
            cp_async16(xd + d1 * 4,
                X + ((size_t)(grp * 8 + f1b) * TT + tn) * 256 + f1q * 4);
        }
        CP_COMMIT();

        // --- gx GEMM first half (c = 0..3). ---
        unsigned long long P0[8], P1[8], P2[8];
#pragma unroll
        for (int b = 0; b < 8; b++) { P0[b] = 0ull; P1[b] = 0ull; P2[b] = 0ull; }

        const float* xb = xs + (s & 1) * 2048;
#pragma unroll
        for (int c = 0; c < 4; c++) {
            const int off = col + ((c ^ ks) & 7) * 4;
            ulonglong2 w0 = *(const ulonglong2*)(wih_s + (jg)      * WPADI + off);
            ulonglong2 w1 = *(const ulonglong2*)(wih_s + (32 + jg) * WPADI + off);
            ulonglong2 w2 = *(const ulonglong2*)(wih_s + (64 + jg) * WPADI + off);
#pragma unroll
            for (int b = 0; b < 8; b++) {
                ulonglong2 hv = *(const ulonglong2*)(xb + b * 256 + off);
                P0[b] = ffma2(w0.x, hv.x, P0[b]);
                P1[b] = ffma2(w1.x, hv.x, P1[b]);
                P2[b] = ffma2(w2.x, hv.x, P2[b]);
                P0[b] = ffma2(w0.y, hv.y, P0[b]);
                P1[b] = ffma2(w1.y, hv.y, P1[b]);
                P2[b] = ffma2(w2.y, hv.y, P2[b]);
            }
        }

        // --- Mid-GEMM: poll peers, then cp.async the h tile (latency hides
        //     under gx half2). ---
        if (s > 0) {
            if (tid < 8) {
                const unsigned* f = &g_flag[dir][grp][tid];
                unsigned v;
                do {
                    asm volatile("ld.acquire.gpu.global.u32 %0, [%1];"
                                 : "=r"(v) : "l"(f) : "memory");
                } while (v < (unsigned)s);
            }
            __syncthreads();
            const float* src = &g_h[dir][s & 1][grp][0][0];
            const uint32_t hd = hs_u + ((s & 1) * 2048) * 4;
            cp_async16(hd + d0 * 4, src + tid * 4);
            cp_async16(hd + d1 * 4, src + (tid + 256) * 4);
            CP_COMMIT();
        }

        // --- gx GEMM second half (c = 4..7). ---
#pragma unroll
        for (int c = 4; c < 8; c++) {
            const int off = col + ((c ^ ks) & 7) * 4;
            ulonglong2 w0 = *(const ulonglong2*)(wih_s + (jg)      * WPADI + off);
            ulonglong2 w1 = *(const ulonglong2*)(wih_s + (32 + jg) * WPADI + off);
            ulonglong2 w2 = *(const ulonglong2*)(wih_s + (64 + jg) * WPADI + off);
#pragma unroll
            for (int b = 0; b < 8; b++) {
                ulonglong2 hv = *(const ulonglong2*)(xb + b * 256 + off);
                P0[b] = ffma2(w0.x, hv.x, P0[b]);
                P1[b] = ffma2(w1.x, hv.x, P1[b]);
                P2[b] = ffma2(w2.x, hv.x, P2[b]);
                P0[b] = ffma2(w0.y, hv.y, P0[b]);
                P1[b] = ffma2(w1.y, hv.y, P1[b]);
                P2[b] = ffma2(w2.y, hv.y, P2[b]);
            }
        }

        // --- All async copies done (h for this step, x for next). ---
        CP_WAIT0();
        __syncthreads();

        // --- Recurrent GEMM: c-outer / b-inner (independent FMA chains
        //     adjacent), W_hh in regs. ---
        const float* hb = hs + (s & 1) * 2048;
#pragma unroll
        for (int c = 0; c < 8; c++) {
            const int off = col + ((c ^ ks) & 7) * 4;
#pragma unroll
            for (int b = 0; b < 8; b++) {
                ulonglong2 hv = *(const ulonglong2*)(hb + b * 256 + off);
                P0[b] = ffma2(w0r[2 * c],     hv.x, P0[b]);
                P1[b] = ffma2(w1r[2 * c],     hv.x, P1[b]);
                P2[b] = ffma2(w2r[2 * c],     hv.x, P2[b]);
                P0[b] = ffma2(w0r[2 * c + 1], hv.y, P0[b]);
                P1[b] = ffma2(w1r[2 * c + 1], hv.y, P1[b]);
                P2[b] = ffma2(w2r[2 * c + 1], hv.y, P2[b]);
            }
        }

        float a0[8], a1[8], a2[8];
#pragma unroll
        for (int b = 0; b < 8; b++) {
            a0[b] = pair_sum(P0[b]);
            a1[b] = pair_sum(P1[b]);
            a2[b] = pair_sum(P2[b]);
        }

        // --- Butterfly reduce-scatter over ks: lane ks owns batch b=ks. ---
        const bool hi4 = (ks & 4) != 0;
        float t0a[4], t1a[4], t2a[4];
#pragma unroll
        for (int i = 0; i < 4; i++) {
            float s0 = hi4 ? a0[i] : a0[i + 4];
            float s1 = hi4 ? a1[i] : a1[i + 4];
            float s2 = hi4 ? a2[i] : a2[i + 4];
            t0a[i] = (hi4 ? a0[i + 4] : a0[i]) + __shfl_xor_sync(0xffffffffu, s0, 4);
            t1a[i] = (hi4 ? a1[i + 4] : a1[i]) + __shfl_xor_sync(0xffffffffu, s1, 4);
            t2a[i] = (hi4 ? a2[i + 4] : a2[i]) + __shfl_xor_sync(0xffffffffu, s2, 4);
        }
        const bool hi2 = (ks & 2) != 0;
        float u0[2], u1[2], u2[2];
#pragma unroll
        for (int i = 0; i < 2; i++) {
            float s0 = hi2 ? t0a[i] : t0a[i + 2];
            float s1 = hi2 ? t1a[i] : t1a[i + 2];
            float s2 = hi2 ? t2a[i] : t2a[i + 2];
            u0[i] = (hi2 ? t0a[i + 2] : t0a[i]) + __shfl_xor_sync(0xffffffffu, s0, 2);
            u1[i] = (hi2 ? t1a[i + 2] : t1a[i]) + __shfl_xor_sync(0xffffffffu, s1, 2);
            u2[i] = (hi2 ? t2a[i + 2] : t2a[i]) + __shfl_xor_sync(0xffffffffu, s2, 2);
        }
        const bool hi1 = (ks & 1) != 0;
        float s0 = hi1 ? u0[0] : u0[1];
        float s1 = hi1 ? u1[0] : u1[1];
        float s2 = hi1 ? u2[0] : u2[1];
        float f0 = (hi1 ? u0[1] : u0[0]) + __shfl_xor_sync(0xffffffffu, s0, 1);
        float f1 = (hi1 ? u1[1] : u1[0]) + __shfl_xor_sync(0xffffffffu, s1, 1);
        float f2 = (hi1 ? u2[1] : u2[0]) + __shfl_xor_sync(0xffffffffu, s2, 1);

        f0 += bias0; f1 += bias1; f2 += bias2;

        // --- Coupled-gate pointwise for (hidden j, batch bG). ---
        float ig = fast_sigmoid(f0);
        float cg = fast_tanh(f1);
        float og = fast_sigmoid(f2);
        c_reg = (1.0f - ig) * c_reg + ig * cg;
        float h = og * fast_tanh(c_reg);

        if (s == TT - 1) {
            st_stream(&out[(size_t)t * (BB * 2 * HH) + (size_t)bG * (2 * HH)
                           + dir * HH + j], h);
            size_t base = (size_t)TT * BB * 2 * HH;
            st_stream(&out[base + (size_t)bG * (2 * HH) + dir * HH + j], h);
            st_stream(&out[base + (size_t)BB * 2 * HH
                           + (size_t)bG * (2 * HH) + dir * HH + j], c_reg);
        } else {
            // Publish h slice; sync; release flag; stream output store.
            g_h[dir][(s + 1) & 1][grp][ks][j] = h;
            __syncthreads();
            if (tid == 0)
                asm volatile("st.release.gpu.global.u32 [%0], %1;"
                             :: "l"(&g_flag[dir][grp][sl]),
                                "r"((unsigned)(s + 1)) : "memory");
            st_stream(&out[(size_t)t * (BB * 2 * HH) + (size_t)bG * (2 * HH)
                           + dir * HH + j], h);
        }
    }
}

// ---------------------------------------------------------------------------
// Launch. Inputs: X, wih_f, whh_f, bih_f, bhh_f, wih_b, whh_b, bih_b, bhh_b.
// Output fp32: out[T,B,2H] ++ hn[1,B,2H] ++ cn[1,B,2H].
// ---------------------------------------------------------------------------
extern "C" void kernel_launch(void* const* d_in, const int* in_sizes, int n_in,
                              void* d_out, int out_size) {
    const float* X     = (const float*)d_in[0];
    const float* wih_f = (const float*)d_in[1];
    const float* whh_f = (const float*)d_in[2];
    const float* bih_f = (const float*)d_in[3];
    const float* bhh_f = (const float*)d_in[4];
    const float* wih_b = (const float*)d_in[5];
    const float* whh_b = (const float*)d_in[6];
    const float* bih_b = (const float*)d_in[7];
    const float* bhh_b = (const float*)d_in[8];
    float* out = (float*)d_out;

    const int smem = (96 * WPADI + 2 * 2048 + 2 * 2048) * (int)sizeof(float);
    cudaFuncSetAttribute(lstm_fused, cudaFuncAttributeMaxDynamicSharedMemorySize,
                         smem);

    lstm_fused<<<128, 256, smem>>>(X, wih_f, whh_f, bih_f, bhh_f,
                                   wih_b, whh_b, bih_b, bhh_b, out);
}

// round 10
// speedup vs baseline: 1.3261x; 1.0187x over previous
#include <cuda_runtime.h>
#include <cstdint>
#include <cstddef>

// Problem dims
#define TT 1024
#define BB 64
#define HH 256
#define WPADI 260   // wih SMEM row stride (floats)

// Dual-direction fused persistent kernel.
// 128 CTAs x 256 threads. Warps 0-3 = dir0 half, warps 4-7 = dir1 half.
// Each half: 16 hidden (48 gate rows) x 8 batches, K=256 both GEMMs.
// Per (dir,grp): 16 halves (one per slice) exchange h via L2 + flags.
// Halves sync via named barriers only -> each SMSP interleaves two
// independent chains (dir0 + dir1), hiding each other's latency.
// Thread (jg 0..15, ks 0..7): 3 gate rows x 32-k slice; W_hh in registers.

__device__ float    g_h[2][2][8][8][256];   // [dir][buf][grp][b][k]
__device__ unsigned g_flag[2][8][16];       // per (dir,grp,slice) step flag
__device__ unsigned g_cnt[16 * 32];         // init barrier (128B-strided)
__device__ unsigned g_phs[16 * 32];

// ---------------------------------------------------------------------------
// Helpers
// ---------------------------------------------------------------------------
__device__ __forceinline__ unsigned long long ffma2(
    unsigned long long a, unsigned long long b, unsigned long long c) {
    unsigned long long d;
    asm("fma.rn.f32x2 %0, %1, %2, %3;" : "=l"(d) : "l"(a), "l"(b), "l"(c));
    return d;
}
__device__ __forceinline__ float pair_sum(unsigned long long p) {
    float lo, hi;
    asm("mov.b64 {%0, %1}, %2;" : "=f"(lo), "=f"(hi) : "l"(p));
    return lo + hi;
}
__device__ __forceinline__ float fast_sigmoid(float x) {
    return 1.0f / (1.0f + __expf(-x));
}
__device__ __forceinline__ float fast_tanh(float x) {
    return 2.0f / (1.0f + __expf(-2.0f * x)) - 1.0f;
}
__device__ __forceinline__ uint32_t smem_u32(const void* p) {
    uint32_t a;
    asm("{ .reg .u64 t; cvta.to.shared.u64 t, %1; cvt.u32.u64 %0, t; }"
        : "=r"(a) : "l"(p));
    return a;
}
__device__ __forceinline__ void cp_async16(uint32_t dst, const void* src) {
    asm volatile("cp.async.cg.shared.global [%0], [%1], 16;"
                 :: "r"(dst), "l"(src) : "memory");
}
#define CP_COMMIT() asm volatile("cp.async.commit_group;" ::: "memory")
#define CP_WAIT0()  asm volatile("cp.async.wait_group 0;" ::: "memory")
__device__ __forceinline__ void st_stream(float* p, float v) {
    asm volatile("st.global.cs.f32 [%0], %1;" :: "l"(p), "f"(v) : "memory");
}
// Per-half named barrier (128 threads). bar id 1 or 2.
__device__ __forceinline__ void half_bar(int half) {
    asm volatile("bar.sync %0, 128;" :: "r"(half + 1) : "memory");
}
// float4-chunk swizzle within a 256-float row (64 chunks of 16B).
__device__ __forceinline__ int swz(int q) {
    return (q & ~7) | ((q ^ (q >> 3)) & 7);
}

// ---------------------------------------------------------------------------
// Dual-direction fused LSTM kernel. grid=128, block=256.
// ---------------------------------------------------------------------------
__global__ void __launch_bounds__(256, 1) lstm_fused(
    const float* __restrict__ X,
    const float* __restrict__ wih_f, const float* __restrict__ whh_f,
    const float* __restrict__ bih_f, const float* __restrict__ bhh_f,
    const float* __restrict__ wih_b, const float* __restrict__ whh_b,
    const float* __restrict__ bih_b, const float* __restrict__ bhh_b,
    float* __restrict__ out)
{
    extern __shared__ float sm[];
    // Layout: wih(dir0), wih(dir1), hs(dir0), hs(dir1), xs(dir0), xs(dir1)
    const int tid  = threadIdx.x;
    const int half = tid >> 7;          // 0 = dir0, 1 = dir1
    const int tidh = tid & 127;
    const int dir  = half;

    float* wih_s = sm + half * (48 * WPADI);
    float* hs    = sm + 2 * (48 * WPADI) + half * (2 * 2048);
    float* xs    = sm + 2 * (48 * WPADI) + 2 * (2 * 2048) + half * (2 * 2048);

    const int bx  = blockIdx.x;
    const int grp = bx & 7;
    const int sl  = bx >> 3;            // 0..15
    const int j0  = sl * 16;
    const int gi  = dir * 8 + grp;

    const float* whh = dir ? whh_b : whh_f;
    const float* wih = dir ? wih_b : wih_f;
    const float* bih = dir ? bih_b : bih_f;
    const float* bhh = dir ? bhh_b : bhh_f;

    const int lane  = tid & 31;
    const int warph = tidh >> 5;               // 0..3 within half
    const int jg    = warph * 4 + (lane >> 3); // hidden within slice 0..15
    const int ks    = lane & 7;                // k-slice 0..7
    const int j     = j0 + jg;
    const int bG    = grp * 8 + ks;
    const int col   = ks * 32;

    // Staging indices: 4 float4 per thread (512 chunks per 8x256 tile).
    int dsw[4], fqv[4], fbv[4];
#pragma unroll
    for (int i = 0; i < 4; i++) {
        int fid = tidh + i * 128;
        fbv[i] = fid >> 6;
        fqv[i] = fid & 63;
        dsw[i] = fbv[i] * 256 + swz(fqv[i]) * 4;
    }
    const uint32_t hs_u = smem_u32(hs);
    const uint32_t xs_u = smem_u32(xs);

    // --- W_hh slice into REGISTERS: 3 rows x 32 k = 48 f32x2. ---
    unsigned long long w0r[16], w1r[16], w2r[16];
#pragma unroll
    for (int g = 0; g < 3; g++) {
        const float* base = whh + (size_t)(g * 256 + j) * 256 + col;
        unsigned long long* dst = (g == 0) ? w0r : (g == 1) ? w1r : w2r;
#pragma unroll
        for (int c = 0; c < 8; c++) {
            ulonglong2 wv = *(const ulonglong2*)(base + c * 4);
            dst[2 * c]     = wv.x;
            dst[2 * c + 1] = wv.y;
        }
    }

    // --- W_ih slice into SMEM (swizzled 16B chunks): 48 rows x 64 chunks. ---
    for (int idx = tidh; idx < 48 * 64; idx += 128) {
        int r = idx >> 6, q = idx & 63;
        int grow = (r >> 4) * 256 + j0 + (r & 15);
        float4 v = *(const float4*)(wih + (size_t)grow * 256 + q * 4);
        *(float4*)(wih_s + r * WPADI + swz(q) * 4) = v;
    }

    const float bias0 = bih[j]       + bhh[j];
    const float bias1 = bih[256 + j] + bhh[256 + j];
    const float bias2 = bih[512 + j] + bhh[512 + j];

    // Zero h buffer 0; stage x for t0.
    for (int idx = tidh; idx < 2048; idx += 128) hs[idx] = 0.0f;
    {
        const int t0 = dir ? (TT - 1) : 0;
#pragma unroll
        for (int i = 0; i < 4; i++) {
            float4 v = __ldcg((const float4*)(
                X + ((size_t)(grp * 8 + fbv[i]) * TT + t0) * 256 + fqv[i] * 4));
            *(float4*)(xs + dsw[i]) = v;
        }
    }
    if (tidh == 0)
        asm volatile("st.relaxed.gpu.global.u32 [%0], %1;"
                     :: "l"(&g_flag[dir][grp][sl]), "r"(0u) : "memory");

    // One-time replay-safe group barrier (16 halves per (dir,grp)).
    half_bar(half);
    if (tidh == 0) {
        unsigned* cnt = &g_cnt[gi * 32];
        unsigned* phs = &g_phs[gi * 32];
        unsigned ph;
        asm volatile("ld.acquire.gpu.global.u32 %0, [%1];"
                     : "=r"(ph) : "l"(phs) : "memory");
        unsigned prev;
        asm volatile("atom.acq_rel.gpu.global.add.u32 %0, [%1], %2;"
                     : "=r"(prev) : "l"(cnt), "r"(1u) : "memory");
        if (prev == 15u) {
            asm volatile("st.relaxed.gpu.global.u32 [%0], %1;"
                         :: "l"(cnt), "r"(0u) : "memory");
            asm volatile("red.release.gpu.global.add.u32 [%0], %1;"
                         :: "l"(phs), "r"(1u) : "memory");
        } else {
            unsigned cur;
            do {
                asm volatile("ld.acquire.gpu.global.u32 %0, [%1];"
                             : "=r"(cur) : "l"(phs) : "memory");
            } while (cur == ph);
        }
    }
    half_bar(half);

    float c_reg = 0.0f;

    for (int s = 0; s < TT; s++) {
        const int t = dir ? (TT - 1 - s) : s;

        // --- Kick x(s+1) prefetch via cp.async. ---
        if (s + 1 < TT) {
            const int tn = dir ? (t - 1) : (t + 1);
            const uint32_t xd = xs_u + (((s + 1) & 1) * 2048) * 4;
#pragma unroll
            for (int i = 0; i < 4; i++)
                cp_async16(xd + dsw[i] * 4,
                    X + ((size_t)(grp * 8 + fbv[i]) * TT + tn) * 256 + fqv[i] * 4);
        }
        CP_COMMIT();

        // --- gx GEMM first half (c = 0..3). ---
        unsigned long long P0[8], P1[8], P2[8];
#pragma unroll
        for (int b = 0; b < 8; b++) { P0[b] = 0ull; P1[b] = 0ull; P2[b] = 0ull; }

        const float* xb = xs + (s & 1) * 2048;
#pragma unroll
        for (int c = 0; c < 4; c++) {
            const int off = col + ((c ^ ks) & 7) * 4;
            ulonglong2 w0 = *(const ulonglong2*)(wih_s + (jg)      * WPADI + off);
            ulonglong2 w1 = *(const ulonglong2*)(wih_s + (16 + jg) * WPADI + off);
            ulonglong2 w2 = *(const ulonglong2*)(wih_s + (32 + jg) * WPADI + off);
#pragma unroll
            for (int b = 0; b < 8; b++) {
                ulonglong2 hv = *(const ulonglong2*)(xb + b * 256 + off);
                P0[b] = ffma2(w0.x, hv.x, P0[b]);
                P1[b] = ffma2(w1.x, hv.x, P1[b]);
                P2[b] = ffma2(w2.x, hv.x, P2[b]);
                P0[b] = ffma2(w0.y, hv.y, P0[b]);
                P1[b] = ffma2(w1.y, hv.y, P1[b]);
                P2[b] = ffma2(w2.y, hv.y, P2[b]);
            }
        }

        // --- Mid-GEMM: poll 16 peer flags, then cp.async the h tile. ---
        if (s > 0) {
            if (tidh < 16) {
                const unsigned* f = &g_flag[dir][grp][tidh];
                unsigned v;
                do {
                    asm volatile("ld.acquire.gpu.global.u32 %0, [%1];"
                                 : "=r"(v) : "l"(f) : "memory");
                } while (v < (unsigned)s);
            }
            half_bar(half);
            const float* src = &g_h[dir][s & 1][grp][0][0];
            const uint32_t hd = hs_u + ((s & 1) * 2048) * 4;
#pragma unroll
            for (int i = 0; i < 4; i++)
                cp_async16(hd + dsw[i] * 4, src + (tidh + i * 128) * 4);
            CP_COMMIT();
        }

        // --- gx GEMM second half (c = 4..7). ---
#pragma unroll
        for (int c = 4; c < 8; c++) {
            const int off = col + ((c ^ ks) & 7) * 4;
            ulonglong2 w0 = *(const ulonglong2*)(wih_s + (jg)      * WPADI + off);
            ulonglong2 w1 = *(const ulonglong2*)(wih_s + (16 + jg) * WPADI + off);
            ulonglong2 w2 = *(const ulonglong2*)(wih_s + (32 + jg) * WPADI + off);
#pragma unroll
            for (int b = 0; b < 8; b++) {
                ulonglong2 hv = *(const ulonglong2*)(xb + b * 256 + off);
                P0[b] = ffma2(w0.x, hv.x, P0[b]);
                P1[b] = ffma2(w1.x, hv.x, P1[b]);
                P2[b] = ffma2(w2.x, hv.x, P2[b]);
                P0[b] = ffma2(w0.y, hv.y, P0[b]);
                P1[b] = ffma2(w1.y, hv.y, P1[b]);
                P2[b] = ffma2(w2.y, hv.y, P2[b]);
            }
        }

        // --- Async copies done (h this step, x next step). ---
        CP_WAIT0();
        half_bar(half);

        // --- Recurrent GEMM: c-outer / b-inner, W_hh in regs. ---
        const float* hb = hs + (s & 1) * 2048;
#pragma unroll
        for (int c = 0; c < 8; c++) {
            const int off = col + ((c ^ ks) & 7) * 4;
#pragma unroll
            for (int b = 0; b < 8; b++) {
                ulonglong2 hv = *(const ulonglong2*)(hb + b * 256 + off);
                P0[b] = ffma2(w0r[2 * c],     hv.x, P0[b]);
                P1[b] = ffma2(w1r[2 * c],     hv.x, P1[b]);
                P2[b] = ffma2(w2r[2 * c],     hv.x, P2[b]);
                P0[b] = ffma2(w0r[2 * c + 1], hv.y, P0[b]);
                P1[b] = ffma2(w1r[2 * c + 1], hv.y, P1[b]);
                P2[b] = ffma2(w2r[2 * c + 1], hv.y, P2[b]);
            }
        }

        float a0[8], a1[8], a2[8];
#pragma unroll
        for (int b = 0; b < 8; b++) {
            a0[b] = pair_sum(P0[b]);
            a1[b] = pair_sum(P1[b]);
            a2[b] = pair_sum(P2[b]);
        }

        // --- Butterfly reduce-scatter over ks: lane ks owns batch b=ks. ---
        const bool hi4 = (ks & 4) != 0;
        float t0a[4], t1a[4], t2a[4];
#pragma unroll
        for (int i = 0; i < 4; i++) {
            float s0 = hi4 ? a0[i] : a0[i + 4];
            float s1 = hi4 ? a1[i] : a1[i + 4];
            float s2 = hi4 ? a2[i] : a2[i + 4];
            t0a[i] = (hi4 ? a0[i + 4] : a0[i]) + __shfl_xor_sync(0xffffffffu, s0, 4);
            t1a[i] = (hi4 ? a1[i + 4] : a1[i]) + __shfl_xor_sync(0xffffffffu, s1, 4);
            t2a[i] = (hi4 ? a2[i + 4] : a2[i]) + __shfl_xor_sync(0xffffffffu, s2, 4);
        }
        const bool hi2 = (ks & 2) != 0;
        float u0[2], u1[2], u2[2];
#pragma unroll
        for (int i = 0; i < 2; i++) {
            float s0 = hi2 ? t0a[i] : t0a[i + 2];
            float s1 = hi2 ? t1a[i] : t1a[i + 2];
            float s2 = hi2 ? t2a[i] : t2a[i + 2];
            u0[i] = (hi2 ? t0a[i + 2] : t0a[i]) + __shfl_xor_sync(0xffffffffu, s0, 2);
            u1[i] = (hi2 ? t1a[i + 2] : t1a[i]) + __shfl_xor_sync(0xffffffffu, s1, 2);
            u2[i] = (hi2 ? t2a[i + 2] : t2a[i]) + __shfl_xor_sync(0xffffffffu, s2, 2);
        }
        const bool hi1 = (ks & 1) != 0;
        float s0 = hi1 ? u0[0] : u0[1];
        float s1 = hi1 ? u1[0] : u1[1];
        float s2 = hi1 ? u2[0] : u2[1];
        float f0 = (hi1 ? u0[1] : u0[0]) + __shfl_xor_sync(0xffffffffu, s0, 1);
        float f1 = (hi1 ? u1[1] : u1[0]) + __shfl_xor_sync(0xffffffffu, s1, 1);
        float f2 = (hi1 ? u2[1] : u2[0]) + __shfl_xor_sync(0xffffffffu, s2, 1);

        f0 += bias0; f1 += bias1; f2 += bias2;

        // --- Coupled-gate pointwise for (hidden j, batch bG). ---
        float ig = fast_sigmoid(f0);
        float cg = fast_tanh(f1);
        float og = fast_sigmoid(f2);
        c_reg = (1.0f - ig) * c_reg + ig * cg;
        float h = og * fast_tanh(c_reg);

        if (s == TT - 1) {
            st_stream(&out[(size_t)t * (BB * 2 * HH) + (size_t)bG * (2 * HH)
                           + dir * HH + j], h);
            size_t base = (size_t)TT * BB * 2 * HH;
            st_stream(&out[base + (size_t)bG * (2 * HH) + dir * HH + j], h);
            st_stream(&out[base + (size_t)BB * 2 * HH
                           + (size_t)bG * (2 * HH) + dir * HH + j], c_reg);
        } else {
            // Publish h slice; half barrier; release flag; stream output.
            g_h[dir][(s + 1) & 1][grp][ks][j] = h;
            half_bar(half);
            if (tidh == 0)
                asm volatile("st.release.gpu.global.u32 [%0], %1;"
                             :: "l"(&g_flag[dir][grp][sl]),
                                "r"((unsigned)(s + 1)) : "memory");
            st_stream(&out[(size_t)t * (BB * 2 * HH) + (size_t)bG * (2 * HH)
                           + dir * HH + j], h);
        }
    }
}

// ---------------------------------------------------------------------------
// Launch. Inputs: X, wih_f, whh_f, bih_f, bhh_f, wih_b, whh_b, bih_b, bhh_b.
// Output fp32: out[T,B,2H] ++ hn[1,B,2H] ++ cn[1,B,2H].
// ---------------------------------------------------------------------------
extern "C" void kernel_launch(void* const* d_in, const int* in_sizes, int n_in,
                              void* d_out, int out_size) {
    const float* X     = (const float*)d_in[0];
    const float* wih_f = (const float*)d_in[1];
    const float* whh_f = (const float*)d_in[2];
    const float* bih_f = (const float*)d_in[3];
    const float* bhh_f = (const float*)d_in[4];
    const float* wih_b = (const float*)d_in[5];
    const float* whh_b = (const float*)d_in[6];
    const float* bih_b = (const float*)d_in[7];
    const float* bhh_b = (const float*)d_in[8];
    float* out = (float*)d_out;

    const int smem = (2 * 48 * WPADI + 4 * 2048 + 4 * 2048) * (int)sizeof(float);
    cudaFuncSetAttribute(lstm_fused, cudaFuncAttributeMaxDynamicSharedMemorySize,
                         smem);

    lstm_fused<<<128, 256, smem>>>(X, wih_f, whh_f, bih_f, bhh_f,
                                   wih_b, whh_b, bih_b, bhh_b, out);
}